// round 1
// baseline (speedup 1.0000x reference)
#include <cuda_runtime.h>
#include <cstdint>

#define DINL __device__ __forceinline__

namespace {
constexpr int NQ   = 3600;    // B*Q
constexpr int KD   = 256;     // query dim
constexpr int NPAR = 32768;   // G * TOTAL
constexpr int TOT  = 8192;
constexpr int SPLITK = 8;
}

// scratch (device globals: allocation-free)
__device__ float g_params[(size_t)NQ * NPAR];               // 472 MB
__device__ float g_h2[(size_t)NQ * NPAR];                   // 472 MB
__device__ float g_psum[(size_t)SPLITK * NQ * KD];          // 29.5 MB

DINL uint32_t f2tf(float x){ uint32_t r; asm("cvt.rna.tf32.f32 %0, %1;" : "=r"(r) : "f"(x)); return r; }
DINL float tf(float x){ return __uint_as_float(f2tf(x)); }
DINL uint32_t fu(float x){ return __float_as_uint(x); }

DINL void mma_tf32(float d[4], float a0,float a1,float a2,float a3, float b0,float b1){
    asm volatile("mma.sync.aligned.m16n8k8.row.col.f32.tf32.tf32.f32 "
                 "{%0,%1,%2,%3}, {%4,%5,%6,%7}, {%8,%9}, {%0,%1,%2,%3};"
                 : "+f"(d[0]),"+f"(d[1]),"+f"(d[2]),"+f"(d[3])
                 : "r"(fu(a0)),"r"(fu(a1)),"r"(fu(a2)),"r"(fu(a3)),"r"(fu(b0)),"r"(fu(b1)));
}

// ---------------------------------------------------------------------------
// K1: params = query @ Wp + bp    [3600,256] x [256,32768] -> g_params
// Tiles: BM=128, BN=128, BK=16. 8 warps (2x4), warp tile 64x32.
// ---------------------------------------------------------------------------
__global__ __launch_bounds__(256) void k_params(const float* __restrict__ A,
                                                const float* __restrict__ B,
                                                const float* __restrict__ bp)
{
    __shared__ float As[16][132];   // [k][m] (transposed), tf32-rounded
    __shared__ float Bs[16][132];   // [k][n], tf32-rounded

    const int tx = threadIdx.x;
    const int bn = blockIdx.x;      // 256 n-tiles
    const int bm = blockIdx.y;      // 29 m-tiles
    const int lane = tx & 31, wid = tx >> 5;
    const int gid = lane >> 2, tig = lane & 3;
    const int wm = (wid >> 2) * 64, wn = (wid & 3) * 32;

    const int arow = tx >> 2, ac = (tx & 3) * 4;  // A tile loads
    const int brow = wid,    bc = lane * 4;       // B tile loads

    float acc[4][4][4];
    #pragma unroll
    for (int i=0;i<4;i++){ for (int j=0;j<4;j++){ for (int q=0;q<4;q++) acc[i][j][q]=0.f; } }

    float4 ap[2], bpre[2];
    #pragma unroll
    for (int j=0;j<2;j++){
        int m = bm*128 + arow + j*64;
        ap[j] = (m < NQ) ? *reinterpret_cast<const float4*>(&A[(size_t)m*KD + ac])
                         : make_float4(0.f,0.f,0.f,0.f);
        bpre[j] = *reinterpret_cast<const float4*>(&B[(size_t)(brow + j*8)*NPAR + bn*128 + bc]);
    }

    #pragma unroll 1
    for (int ks=0; ks<16; ks++){
        #pragma unroll
        for (int j=0;j<2;j++){
            int m = arow + j*64;
            As[ac+0][m]=tf(ap[j].x); As[ac+1][m]=tf(ap[j].y);
            As[ac+2][m]=tf(ap[j].z); As[ac+3][m]=tf(ap[j].w);
            int kr = brow + j*8;
            Bs[kr][bc+0]=tf(bpre[j].x); Bs[kr][bc+1]=tf(bpre[j].y);
            Bs[kr][bc+2]=tf(bpre[j].z); Bs[kr][bc+3]=tf(bpre[j].w);
        }
        __syncthreads();
        if (ks < 15){
            int k0 = (ks+1)*16;
            #pragma unroll
            for (int j=0;j<2;j++){
                int m = bm*128 + arow + j*64;
                ap[j] = (m < NQ) ? *reinterpret_cast<const float4*>(&A[(size_t)m*KD + k0 + ac])
                                 : make_float4(0.f,0.f,0.f,0.f);
                bpre[j] = *reinterpret_cast<const float4*>(&B[(size_t)(k0 + brow + j*8)*NPAR + bn*128 + bc]);
            }
        }
        #pragma unroll
        for (int kk=0; kk<2; kk++){
            float af[4][4], bf[4][2];
            #pragma unroll
            for (int mi=0;mi<4;mi++){
                int m = wm + mi*16 + gid;
                af[mi][0]=As[kk*8+tig][m];   af[mi][1]=As[kk*8+tig][m+8];
                af[mi][2]=As[kk*8+tig+4][m]; af[mi][3]=As[kk*8+tig+4][m+8];
            }
            #pragma unroll
            for (int ni=0;ni<4;ni++){
                int nn = wn + ni*8 + gid;
                bf[ni][0]=Bs[kk*8+tig][nn];
                bf[ni][1]=Bs[kk*8+tig+4][nn];
            }
            #pragma unroll
            for (int mi=0;mi<4;mi++){
                #pragma unroll
                for (int ni=0;ni<4;ni++)
                    mma_tf32(acc[mi][ni], af[mi][0],af[mi][1],af[mi][2],af[mi][3],
                             bf[ni][0],bf[ni][1]);
            }
        }
        __syncthreads();
    }

    #pragma unroll
    for (int mi=0;mi<4;mi++){
        int r0 = bm*128 + wm + mi*16 + gid;
        #pragma unroll
        for (int ni=0;ni<4;ni++){
            int c0 = bn*128 + wn + ni*8 + tig*2;
            float b0v = bp[c0], b1v = bp[c0+1];
            if (r0 < NQ){
                float2 v = make_float2(acc[mi][ni][0]+b0v, acc[mi][ni][1]+b1v);
                *reinterpret_cast<float2*>(&g_params[(size_t)r0*NPAR + c0]) = v;
            }
            if (r0+8 < NQ){
                float2 v = make_float2(acc[mi][ni][2]+b0v, acc[mi][ni][3]+b1v);
                *reinterpret_cast<float2*>(&g_params[(size_t)(r0+8)*NPAR + c0]) = v;
            }
        }
    }
}

// ---------------------------------------------------------------------------
// K2: per (n,g) mixing: out1 = x@M -> LN -> relu -> out2 = S@h1 -> LN -> relu
// One CTA of 256 threads per (n,g). Everything in smem, fp32 exact.
// ---------------------------------------------------------------------------
DINL void block_stats(int t, float s, float s2, float invN, volatile float* red,
                      float& mu, float& rstd)
{
    #pragma unroll
    for (int off=16; off>0; off>>=1){
        s  += __shfl_xor_sync(0xffffffffu, s,  off);
        s2 += __shfl_xor_sync(0xffffffffu, s2, off);
    }
    const int wid = t >> 5;
    if ((t & 31) == 0){ red[wid] = s; red[8+wid] = s2; }
    __syncthreads();
    if (t == 0){
        float S=0.f, S2=0.f;
        #pragma unroll
        for (int i=0;i<8;i++){ S += red[i]; S2 += red[8+i]; }
        float m = S*invN;
        float v = S2*invN - m*m;
        red[16] = m;
        red[17] = rsqrtf(v + 1e-5f);
    }
    __syncthreads();
    mu = red[16]; rstd = red[17];
}

__global__ __launch_bounds__(256) void k_mix(const float* __restrict__ x)
{
    __shared__ float sM[64*64];    // [c][o]
    __shared__ float sS[128*32];   // [qp][p]
    __shared__ float sX[32*64];    // [p][c], reused as h1 [p][o]
    __shared__ float sRed[18];

    const int g = blockIdx.x;      // 4
    const int n = blockIdx.y;      // 3600
    const int t = threadIdx.x;

    const float* pbase = g_params + (size_t)n*NPAR + (size_t)g*TOT;
    #pragma unroll
    for (int i=0;i<4;i++)
        reinterpret_cast<float4*>(sM)[t + i*256] = reinterpret_cast<const float4*>(pbase)[t + i*256];
    #pragma unroll
    for (int i=0;i<4;i++)
        reinterpret_cast<float4*>(sS)[t + i*256] = reinterpret_cast<const float4*>(pbase + 4096)[t + i*256];
    const float* xb = x + (size_t)(n*4 + g) * 2048;
    #pragma unroll
    for (int i=0;i<2;i++)
        reinterpret_cast<float4*>(sX)[t + i*256] = reinterpret_cast<const float4*>(xb)[t + i*256];
    __syncthreads();

    const int o0 = (t & 15) * 4;   // output column base (4 cols)
    const int r0 = t >> 4;         // 0..15

    // --- out1[p][o] = sum_c x[p][c] * M[c][o];  p in {r0, r0+16} ---
    float a1[2][4];
    #pragma unroll
    for (int i=0;i<2;i++){ a1[i][0]=0.f;a1[i][1]=0.f;a1[i][2]=0.f;a1[i][3]=0.f; }
    #pragma unroll 8
    for (int c=0;c<64;c++){
        float4 mv = *reinterpret_cast<const float4*>(&sM[c*64 + o0]);
        float x0 = sX[r0*64 + c];
        float x1 = sX[(r0+16)*64 + c];
        a1[0][0]=fmaf(x0,mv.x,a1[0][0]); a1[0][1]=fmaf(x0,mv.y,a1[0][1]);
        a1[0][2]=fmaf(x0,mv.z,a1[0][2]); a1[0][3]=fmaf(x0,mv.w,a1[0][3]);
        a1[1][0]=fmaf(x1,mv.x,a1[1][0]); a1[1][1]=fmaf(x1,mv.y,a1[1][1]);
        a1[1][2]=fmaf(x1,mv.z,a1[1][2]); a1[1][3]=fmaf(x1,mv.w,a1[1][3]);
    }
    float s=0.f, s2=0.f;
    #pragma unroll
    for (int i=0;i<2;i++){ for (int j=0;j<4;j++){ s += a1[i][j]; s2 = fmaf(a1[i][j],a1[i][j],s2); } }
    float mu, rstd;
    block_stats(t, s, s2, 1.f/2048.f, sRed, mu, rstd);

    float* sH = sX;  // safe: all sX reads completed before block_stats' barrier
    #pragma unroll
    for (int i=0;i<2;i++){
        float4 hv;
        hv.x = fmaxf(0.f, (a1[i][0]-mu)*rstd);
        hv.y = fmaxf(0.f, (a1[i][1]-mu)*rstd);
        hv.z = fmaxf(0.f, (a1[i][2]-mu)*rstd);
        hv.w = fmaxf(0.f, (a1[i][3]-mu)*rstd);
        *reinterpret_cast<float4*>(&sH[(r0+16*i)*64 + o0]) = hv;
    }
    __syncthreads();

    // --- out2[qp][o] = sum_p S[qp][p] * h1[p][o];  qp in {r0+16i, i<8} ---
    float a2[8][4];
    #pragma unroll
    for (int i=0;i<8;i++){ a2[i][0]=0.f;a2[i][1]=0.f;a2[i][2]=0.f;a2[i][3]=0.f; }
    #pragma unroll 4
    for (int p=0;p<32;p++){
        float4 hv = *reinterpret_cast<const float4*>(&sH[p*64 + o0]);
        #pragma unroll
        for (int i=0;i<8;i++){
            float sv = sS[(r0+16*i)*32 + p];
            a2[i][0]=fmaf(sv,hv.x,a2[i][0]); a2[i][1]=fmaf(sv,hv.y,a2[i][1]);
            a2[i][2]=fmaf(sv,hv.z,a2[i][2]); a2[i][3]=fmaf(sv,hv.w,a2[i][3]);
        }
    }
    s=0.f; s2=0.f;
    #pragma unroll
    for (int i=0;i<8;i++){ for (int j=0;j<4;j++){ s += a2[i][j]; s2 = fmaf(a2[i][j],a2[i][j],s2); } }
    float mu2, rstd2;
    block_stats(t, s, s2, 1.f/8192.f, sRed, mu2, rstd2);

    float* outp = g_h2 + (size_t)n*NPAR + (size_t)g*TOT;
    #pragma unroll
    for (int i=0;i<8;i++){
        float4 v;
        v.x = fmaxf(0.f, (a2[i][0]-mu2)*rstd2);
        v.y = fmaxf(0.f, (a2[i][1]-mu2)*rstd2);
        v.z = fmaxf(0.f, (a2[i][2]-mu2)*rstd2);
        v.w = fmaxf(0.f, (a2[i][3]-mu2)*rstd2);
        *reinterpret_cast<float4*>(&outp[(r0+16*i)*64 + o0]) = v;
    }
}

// ---------------------------------------------------------------------------
// K3: psum[sk] = h2[:, sk-slice] @ Wo[sk-slice, :]
// BM=64, BN=256, BK=16, split-K=8 (fixed, deterministic). 57x8 CTAs.
// ---------------------------------------------------------------------------
__global__ __launch_bounds__(256) void k_proj(const float* __restrict__ Wo)
{
    __shared__ float As[16][68];    // [k][m] transposed, tf32-rounded
    __shared__ float Bs[16][260];   // [k][n], tf32-rounded

    const int tx = threadIdx.x;
    const int bm = blockIdx.x;      // 57
    const int sk = blockIdx.y;      // 8
    const int lane = tx & 31, wid = tx >> 5;
    const int gid = lane >> 2, tig = lane & 3;
    const int wm = (wid >> 2) * 32, wn = (wid & 3) * 64;

    const int arow = tx >> 2, ac = (tx & 3) * 4;
    const int brow = tx >> 6, bc = (tx & 63) * 4;
    const int am = bm*64 + arow;
    const bool avalid = (am < NQ);
    const int k0 = sk * 4096;

    float acc[2][8][4];
    #pragma unroll
    for (int i=0;i<2;i++){ for (int j=0;j<8;j++){ for (int q=0;q<4;q++) acc[i][j][q]=0.f; } }

    float4 apre; float4 bpre[4];
    apre = avalid ? *reinterpret_cast<const float4*>(&g_h2[(size_t)am*NPAR + k0 + ac])
                  : make_float4(0.f,0.f,0.f,0.f);
    #pragma unroll
    for (int j=0;j<4;j++)
        bpre[j] = *reinterpret_cast<const float4*>(&Wo[(size_t)(k0 + brow + j*4)*KD + bc]);

    #pragma unroll 1
    for (int ks=0; ks<256; ks++){
        As[ac+0][arow]=tf(apre.x); As[ac+1][arow]=tf(apre.y);
        As[ac+2][arow]=tf(apre.z); As[ac+3][arow]=tf(apre.w);
        #pragma unroll
        for (int j=0;j<4;j++){
            float4 c4 = make_float4(tf(bpre[j].x),tf(bpre[j].y),tf(bpre[j].z),tf(bpre[j].w));
            *reinterpret_cast<float4*>(&Bs[brow + j*4][bc]) = c4;
        }
        __syncthreads();
        if (ks < 255){
            int kn = k0 + (ks+1)*16;
            apre = avalid ? *reinterpret_cast<const float4*>(&g_h2[(size_t)am*NPAR + kn + ac])
                          : make_float4(0.f,0.f,0.f,0.f);
            #pragma unroll
            for (int j=0;j<4;j++)
                bpre[j] = *reinterpret_cast<const float4*>(&Wo[(size_t)(kn + brow + j*4)*KD + bc]);
        }
        #pragma unroll
        for (int kk=0; kk<2; kk++){
            float af[2][4], bf[8][2];
            #pragma unroll
            for (int mi=0;mi<2;mi++){
                int m = wm + mi*16 + gid;
                af[mi][0]=As[kk*8+tig][m];   af[mi][1]=As[kk*8+tig][m+8];
                af[mi][2]=As[kk*8+tig+4][m]; af[mi][3]=As[kk*8+tig+4][m+8];
            }
            #pragma unroll
            for (int ni=0;ni<8;ni++){
                int nn = wn + ni*8 + gid;
                bf[ni][0]=Bs[kk*8+tig][nn];
                bf[ni][1]=Bs[kk*8+tig+4][nn];
            }
            #pragma unroll
            for (int mi=0;mi<2;mi++){
                #pragma unroll
                for (int ni=0;ni<8;ni++)
                    mma_tf32(acc[mi][ni], af[mi][0],af[mi][1],af[mi][2],af[mi][3],
                             bf[ni][0],bf[ni][1]);
            }
        }
        __syncthreads();
    }

    #pragma unroll
    for (int mi=0;mi<2;mi++){
        int r0 = bm*64 + wm + mi*16 + gid;
        #pragma unroll
        for (int ni=0;ni<8;ni++){
            int c0 = wn + ni*8 + tig*2;
            if (r0 < NQ){
                float2 v = make_float2(acc[mi][ni][0], acc[mi][ni][1]);
                *reinterpret_cast<float2*>(&g_psum[((size_t)sk*NQ + r0)*KD + c0]) = v;
            }
            if (r0+8 < NQ){
                float2 v = make_float2(acc[mi][ni][2], acc[mi][ni][3]);
                *reinterpret_cast<float2*>(&g_psum[((size_t)sk*NQ + (r0+8))*KD + c0]) = v;
            }
        }
    }
}

// ---------------------------------------------------------------------------
// K4: out = query + bo + sum_sk psum[sk]
// ---------------------------------------------------------------------------
__global__ __launch_bounds__(256) void k_reduce(const float* __restrict__ query,
                                                const float* __restrict__ bo,
                                                float* __restrict__ out)
{
    int idx = blockIdx.x * 256 + threadIdx.x;   // grid = 3600 -> 921600
    float v = query[idx] + bo[idx & 255];
    #pragma unroll
    for (int s=0;s<SPLITK;s++)
        v += g_psum[(size_t)s*NQ*KD + idx];
    out[idx] = v;
}

// ---------------------------------------------------------------------------
extern "C" void kernel_launch(void* const* d_in, const int* in_sizes, int n_in,
                              void* d_out, int out_size)
{
    const float* x     = (const float*)d_in[0];  // [4,900,4,32,64]
    const float* query = (const float*)d_in[1];  // [4,900,256]
    const float* Wp    = (const float*)d_in[2];  // [256,32768]
    const float* bp    = (const float*)d_in[3];  // [32768]
    const float* Wo    = (const float*)d_in[4];  // [32768,256]
    const float* bo    = (const float*)d_in[5];  // [256]
    float* out = (float*)d_out;

    k_params<<<dim3(256, 29), 256>>>(query, Wp, bp);
    k_mix<<<dim3(4, 3600), 256>>>(x);
    k_proj<<<dim3(57, SPLITK), 256>>>(Wo);
    k_reduce<<<3600, 256>>>(query, bo, out);
}

// round 3
// speedup vs baseline: 1.3220x; 1.3220x over previous
#include <cuda_runtime.h>
#include <cuda_fp16.h>
#include <cstdint>

#define DINL __device__ __forceinline__

namespace {
constexpr int NQ   = 3600;    // B*Q
constexpr int KD   = 256;     // query dim
constexpr int NPAR = 32768;   // G * TOTAL
constexpr int TOT  = 8192;
constexpr int SPLITK = 8;
}

// scratch (device globals: allocation-free)
__device__ __half g_params[(size_t)NQ * NPAR];              // 236 MB
__device__ __half g_h2[(size_t)NQ * NPAR];                  // 236 MB
__device__ float  g_psum[(size_t)SPLITK * NQ * KD];         // 29.5 MB

DINL uint32_t smem_u32(const void* p){ return (uint32_t)__cvta_generic_to_shared(p); }

DINL void ldsm_x4(uint32_t r[4], uint32_t a){
    asm volatile("ldmatrix.sync.aligned.m8n8.x4.shared.b16 {%0,%1,%2,%3}, [%4];"
                 : "=r"(r[0]),"=r"(r[1]),"=r"(r[2]),"=r"(r[3]) : "r"(a));
}
DINL void ldsm_x4_t(uint32_t r[4], uint32_t a){
    asm volatile("ldmatrix.sync.aligned.m8n8.x4.trans.shared.b16 {%0,%1,%2,%3}, [%4];"
                 : "=r"(r[0]),"=r"(r[1]),"=r"(r[2]),"=r"(r[3]) : "r"(a));
}
DINL void mma16816(float d[4], const uint32_t a[4], const uint32_t b[2]){
    asm volatile("mma.sync.aligned.m16n8k16.row.col.f32.f16.f16.f32 "
                 "{%0,%1,%2,%3}, {%4,%5,%6,%7}, {%8,%9}, {%0,%1,%2,%3};"
                 : "+f"(d[0]),"+f"(d[1]),"+f"(d[2]),"+f"(d[3])
                 : "r"(a[0]),"r"(a[1]),"r"(a[2]),"r"(a[3]),"r"(b[0]),"r"(b[1]));
}
DINL uint2 cvt4h(float4 v){
    union { __half2 h[2]; uint2 u; } p;
    p.h[0] = __floats2half2_rn(v.x, v.y);
    p.h[1] = __floats2half2_rn(v.z, v.w);
    return p.u;
}

// ---------------------------------------------------------------------------
// K1: params = half( query @ Wp + bp )   [3600,256] x [256,32768]
// BM=128, BN=128, BK=32, 8 warps (2m x 4n), warp tile 64x32, fp16 MMA.
// ---------------------------------------------------------------------------
__global__ __launch_bounds__(256) void k_params(const float* __restrict__ A,
                                                const float* __restrict__ B,
                                                const float* __restrict__ bp)
{
    __shared__ __half As[128][40];    // [m][k], pad 8
    __shared__ __half Bs[32][136];    // [k][n], pad 8

    const int tx = threadIdx.x;
    const int bn = blockIdx.x;        // 256
    const int bm = blockIdx.y;        // 29
    const int lane = tx & 31, wid = tx >> 5;
    const int g8 = lane >> 2, t4 = lane & 3;
    const int wm = (wid >> 2) * 64, wn = (wid & 3) * 32;

    const int arow = tx >> 1, acol = (tx & 1) * 16;
    const int bk   = tx >> 3, bcol = (tx & 7) * 16;
    const int gm = bm * 128 + arow;
    const bool av = (gm < NQ);

    // ldmatrix lane address components
    const int lr  = (lane & 7) + ((lane >> 3) & 1) * 8;  // row within 16
    const int lc8 = (lane >> 4) * 8;                     // 0 or 8

    float4 apre[4], bpre[4];
    #pragma unroll
    for (int i = 0; i < 4; i++){
        apre[i] = av ? *(const float4*)&A[(size_t)gm*KD + acol + 4*i]
                     : make_float4(0.f,0.f,0.f,0.f);
        bpre[i] = *(const float4*)&B[(size_t)bk*NPAR + (size_t)bn*128 + bcol + 4*i];
    }

    float acc[4][4][4];
    #pragma unroll
    for (int i=0;i<4;i++) for (int j=0;j<4;j++) for (int q=0;q<4;q++) acc[i][j][q]=0.f;

    #pragma unroll 1
    for (int ks = 0; ks < 8; ks++){
        #pragma unroll
        for (int i = 0; i < 4; i++){
            *(uint2*)&As[arow][acol + 4*i] = cvt4h(apre[i]);
            *(uint2*)&Bs[bk][bcol + 4*i]   = cvt4h(bpre[i]);
        }
        __syncthreads();
        if (ks < 7){
            const int k0 = (ks + 1) * 32;
            #pragma unroll
            for (int i = 0; i < 4; i++){
                apre[i] = av ? *(const float4*)&A[(size_t)gm*KD + k0 + acol + 4*i]
                             : make_float4(0.f,0.f,0.f,0.f);
                bpre[i] = *(const float4*)&B[(size_t)(k0+bk)*NPAR + (size_t)bn*128 + bcol + 4*i];
            }
        }
        #pragma unroll
        for (int kk = 0; kk < 32; kk += 16){
            uint32_t af[4][4], bf[4][2];
            #pragma unroll
            for (int mi = 0; mi < 4; mi++)
                ldsm_x4(af[mi], smem_u32(&As[wm + mi*16 + lr][kk + lc8]));
            #pragma unroll
            for (int nj = 0; nj < 2; nj++){
                uint32_t r[4];
                ldsm_x4_t(r, smem_u32(&Bs[kk + lr][wn + nj*16 + lc8]));
                bf[nj*2+0][0]=r[0]; bf[nj*2+0][1]=r[1];
                bf[nj*2+1][0]=r[2]; bf[nj*2+1][1]=r[3];
            }
            #pragma unroll
            for (int mi = 0; mi < 4; mi++)
                #pragma unroll
                for (int ni = 0; ni < 4; ni++)
                    mma16816(acc[mi][ni], af[mi], bf[ni]);
        }
        __syncthreads();
    }

    #pragma unroll
    for (int mi = 0; mi < 4; mi++){
        int r0 = bm*128 + wm + mi*16 + g8;
        #pragma unroll
        for (int ni = 0; ni < 4; ni++){
            int c = bn*128 + wn + ni*8 + t4*2;
            float2 bv = *(const float2*)&bp[c];
            if (r0 < NQ)
                *(__half2*)&g_params[(size_t)r0*NPAR + c] =
                    __floats2half2_rn(acc[mi][ni][0]+bv.x, acc[mi][ni][1]+bv.y);
            if (r0 + 8 < NQ)
                *(__half2*)&g_params[(size_t)(r0+8)*NPAR + c] =
                    __floats2half2_rn(acc[mi][ni][2]+bv.x, acc[mi][ni][3]+bv.y);
        }
    }
}

// ---------------------------------------------------------------------------
// K2: per (n,g) mixing, fp32 compute, half in / half out
// ---------------------------------------------------------------------------
DINL void block_stats(int t, float s, float s2, float invN, volatile float* red,
                      float& mu, float& rstd)
{
    #pragma unroll
    for (int off=16; off>0; off>>=1){
        s  += __shfl_xor_sync(0xffffffffu, s,  off);
        s2 += __shfl_xor_sync(0xffffffffu, s2, off);
    }
    const int wid = t >> 5;
    if ((t & 31) == 0){ red[wid] = s; red[8+wid] = s2; }
    __syncthreads();
    if (t == 0){
        float S=0.f, S2=0.f;
        #pragma unroll
        for (int i=0;i<8;i++){ S += red[i]; S2 += red[8+i]; }
        float m = S*invN;
        float v = S2*invN - m*m;
        red[16] = m;
        red[17] = rsqrtf(v + 1e-5f);
    }
    __syncthreads();
    mu = red[16]; rstd = red[17];
}

__global__ __launch_bounds__(256) void k_mix(const float* __restrict__ x)
{
    __shared__ float sM[64*64];
    __shared__ float sS[128*32];
    __shared__ float sX[32*64];
    __shared__ float sRed[18];

    const int g = blockIdx.x;
    const int n = blockIdx.y;
    const int t = threadIdx.x;

    const uint4* p4 = (const uint4*)(g_params + (size_t)n*NPAR + (size_t)g*TOT);
    #pragma unroll
    for (int i = 0; i < 4; i++){
        int j = t + i*256;                // 0..1023 uint4 (8192 halfs)
        union { uint4 u; __half2 h[4]; } pk; pk.u = p4[j];
        float2 f0 = __half22float2(pk.h[0]);
        float2 f1 = __half22float2(pk.h[1]);
        float2 f2 = __half22float2(pk.h[2]);
        float2 f3 = __half22float2(pk.h[3]);
        float* dst = (j < 512) ? &sM[8*j] : &sS[8*(j-512)];
        *(float4*)dst       = make_float4(f0.x,f0.y,f1.x,f1.y);
        *(float4*)(dst + 4) = make_float4(f2.x,f2.y,f3.x,f3.y);
    }
    const float* xb = x + (size_t)(n*4 + g) * 2048;
    #pragma unroll
    for (int i=0;i<2;i++)
        reinterpret_cast<float4*>(sX)[t + i*256] = reinterpret_cast<const float4*>(xb)[t + i*256];
    __syncthreads();

    const int o0 = (t & 15) * 4;
    const int r0 = t >> 4;

    float a1[2][4];
    #pragma unroll
    for (int i=0;i<2;i++){ a1[i][0]=0.f;a1[i][1]=0.f;a1[i][2]=0.f;a1[i][3]=0.f; }
    #pragma unroll 8
    for (int c=0;c<64;c++){
        float4 mv = *reinterpret_cast<const float4*>(&sM[c*64 + o0]);
        float x0 = sX[r0*64 + c];
        float x1 = sX[(r0+16)*64 + c];
        a1[0][0]=fmaf(x0,mv.x,a1[0][0]); a1[0][1]=fmaf(x0,mv.y,a1[0][1]);
        a1[0][2]=fmaf(x0,mv.z,a1[0][2]); a1[0][3]=fmaf(x0,mv.w,a1[0][3]);
        a1[1][0]=fmaf(x1,mv.x,a1[1][0]); a1[1][1]=fmaf(x1,mv.y,a1[1][1]);
        a1[1][2]=fmaf(x1,mv.z,a1[1][2]); a1[1][3]=fmaf(x1,mv.w,a1[1][3]);
    }
    float s=0.f, s2=0.f;
    #pragma unroll
    for (int i=0;i<2;i++){ for (int j=0;j<4;j++){ s += a1[i][j]; s2 = fmaf(a1[i][j],a1[i][j],s2); } }
    float mu, rstd;
    block_stats(t, s, s2, 1.f/2048.f, sRed, mu, rstd);

    float* sH = sX;  // all sX reads done before block_stats' barrier
    #pragma unroll
    for (int i=0;i<2;i++){
        float4 hv;
        hv.x = fmaxf(0.f, (a1[i][0]-mu)*rstd);
        hv.y = fmaxf(0.f, (a1[i][1]-mu)*rstd);
        hv.z = fmaxf(0.f, (a1[i][2]-mu)*rstd);
        hv.w = fmaxf(0.f, (a1[i][3]-mu)*rstd);
        *reinterpret_cast<float4*>(&sH[(r0+16*i)*64 + o0]) = hv;
    }
    __syncthreads();

    float a2[8][4];
    #pragma unroll
    for (int i=0;i<8;i++){ a2[i][0]=0.f;a2[i][1]=0.f;a2[i][2]=0.f;a2[i][3]=0.f; }
    #pragma unroll 4
    for (int p=0;p<32;p++){
        float4 hv = *reinterpret_cast<const float4*>(&sH[p*64 + o0]);
        #pragma unroll
        for (int i=0;i<8;i++){
            float sv = sS[(r0+16*i)*32 + p];
            a2[i][0]=fmaf(sv,hv.x,a2[i][0]); a2[i][1]=fmaf(sv,hv.y,a2[i][1]);
            a2[i][2]=fmaf(sv,hv.z,a2[i][2]); a2[i][3]=fmaf(sv,hv.w,a2[i][3]);
        }
    }
    s=0.f; s2=0.f;
    #pragma unroll
    for (int i=0;i<8;i++){ for (int j=0;j<4;j++){ s += a2[i][j]; s2 = fmaf(a2[i][j],a2[i][j],s2); } }
    float mu2, rstd2;
    block_stats(t, s, s2, 1.f/8192.f, sRed, mu2, rstd2);

    __half* outp = g_h2 + (size_t)n*NPAR + (size_t)g*TOT;
    #pragma unroll
    for (int i=0;i<8;i++){
        float4 v;
        v.x = fmaxf(0.f, (a2[i][0]-mu2)*rstd2);
        v.y = fmaxf(0.f, (a2[i][1]-mu2)*rstd2);
        v.z = fmaxf(0.f, (a2[i][2]-mu2)*rstd2);
        v.w = fmaxf(0.f, (a2[i][3]-mu2)*rstd2);
        union { __half2 h[2]; uint2 u; } pk;
        pk.h[0] = __floats2half2_rn(v.x, v.y);
        pk.h[1] = __floats2half2_rn(v.z, v.w);
        *(uint2*)&outp[(r0+16*i)*64 + o0] = pk.u;
    }
}

// ---------------------------------------------------------------------------
// K3: psum[sk] = h2[:, sk-slice] @ Wo[sk-slice, :]
// BM=128, BN=128, BK=32, fp16 MMA, fixed split-K=8. grid (29,2,8).
// ---------------------------------------------------------------------------
__global__ __launch_bounds__(256) void k_proj(const float* __restrict__ Wo)
{
    __shared__ __half As[128][40];
    __shared__ __half Bs[32][136];

    const int tx = threadIdx.x;
    const int bm = blockIdx.x;      // 29
    const int bn = blockIdx.y;      // 2
    const int sk = blockIdx.z;      // 8
    const int lane = tx & 31, wid = tx >> 5;
    const int g8 = lane >> 2, t4 = lane & 3;
    const int wm = (wid >> 2) * 64, wn = (wid & 3) * 32;

    const int arow = tx >> 1, acol = (tx & 1) * 16;
    const int bk   = tx >> 3, bcol = (tx & 7) * 16;
    const int gm = bm * 128 + arow;
    const bool av = (gm < NQ);
    const int kbase = sk * 4096;

    const int lr  = (lane & 7) + ((lane >> 3) & 1) * 8;
    const int lc8 = (lane >> 4) * 8;

    uint4 apre[2]; float4 bpre[4];
    #pragma unroll
    for (int i = 0; i < 2; i++)
        apre[i] = av ? *(const uint4*)&g_h2[(size_t)gm*NPAR + kbase + acol + 8*i]
                     : make_uint4(0u,0u,0u,0u);
    #pragma unroll
    for (int i = 0; i < 4; i++)
        bpre[i] = *(const float4*)&Wo[(size_t)(kbase+bk)*KD + bn*128 + bcol + 4*i];

    float acc[4][4][4];
    #pragma unroll
    for (int i=0;i<4;i++) for (int j=0;j<4;j++) for (int q=0;q<4;q++) acc[i][j][q]=0.f;

    #pragma unroll 1
    for (int ks = 0; ks < 128; ks++){
        #pragma unroll
        for (int i = 0; i < 2; i++)
            *(uint4*)&As[arow][acol + 8*i] = apre[i];
        #pragma unroll
        for (int i = 0; i < 4; i++)
            *(uint2*)&Bs[bk][bcol + 4*i] = cvt4h(bpre[i]);
        __syncthreads();
        if (ks < 127){
            const int k0 = kbase + (ks + 1) * 32;
            #pragma unroll
            for (int i = 0; i < 2; i++)
                apre[i] = av ? *(const uint4*)&g_h2[(size_t)gm*NPAR + k0 + acol + 8*i]
                             : make_uint4(0u,0u,0u,0u);
            #pragma unroll
            for (int i = 0; i < 4; i++)
                bpre[i] = *(const float4*)&Wo[(size_t)(k0+bk)*KD + bn*128 + bcol + 4*i];
        }
        #pragma unroll
        for (int kk = 0; kk < 32; kk += 16){
            uint32_t af[4][4], bf[4][2];
            #pragma unroll
            for (int mi = 0; mi < 4; mi++)
                ldsm_x4(af[mi], smem_u32(&As[wm + mi*16 + lr][kk + lc8]));
            #pragma unroll
            for (int nj = 0; nj < 2; nj++){
                uint32_t r[4];
                ldsm_x4_t(r, smem_u32(&Bs[kk + lr][wn + nj*16 + lc8]));
                bf[nj*2+0][0]=r[0]; bf[nj*2+0][1]=r[1];
                bf[nj*2+1][0]=r[2]; bf[nj*2+1][1]=r[3];
            }
            #pragma unroll
            for (int mi = 0; mi < 4; mi++)
                #pragma unroll
                for (int ni = 0; ni < 4; ni++)
                    mma16816(acc[mi][ni], af[mi], bf[ni]);
        }
        __syncthreads();
    }

    #pragma unroll
    for (int mi = 0; mi < 4; mi++){
        int r0 = bm*128 + wm + mi*16 + g8;
        #pragma unroll
        for (int ni = 0; ni < 4; ni++){
            int c = bn*128 + wn + ni*8 + t4*2;
            if (r0 < NQ)
                *(float2*)&g_psum[((size_t)sk*NQ + r0)*KD + c] =
                    make_float2(acc[mi][ni][0], acc[mi][ni][1]);
            if (r0 + 8 < NQ)
                *(float2*)&g_psum[((size_t)sk*NQ + (r0+8))*KD + c] =
                    make_float2(acc[mi][ni][2], acc[mi][ni][3]);
        }
    }
}

// ---------------------------------------------------------------------------
// K4: out = query + bo + sum_sk psum[sk]
// ---------------------------------------------------------------------------
__global__ __launch_bounds__(256) void k_reduce(const float* __restrict__ query,
                                                const float* __restrict__ bo,
                                                float* __restrict__ out)
{
    int idx = blockIdx.x * 256 + threadIdx.x;
    float v = query[idx] + bo[idx & 255];
    #pragma unroll
    for (int s=0;s<SPLITK;s++)
        v += g_psum[(size_t)s*NQ*KD + idx];
    out[idx] = v;
}

// ---------------------------------------------------------------------------
extern "C" void kernel_launch(void* const* d_in, const int* in_sizes, int n_in,
                              void* d_out, int out_size)
{
    const float* x     = (const float*)d_in[0];
    const float* query = (const float*)d_in[1];
    const float* Wp    = (const float*)d_in[2];
    const float* bp    = (const float*)d_in[3];
    const float* Wo    = (const float*)d_in[4];
    const float* bo    = (const float*)d_in[5];
    float* out = (float*)d_out;

    k_params<<<dim3(256, 29), 256>>>(query, Wp, bp);
    k_mix<<<dim3(4, 3600), 256>>>(x);
    k_proj<<<dim3(29, 2, SPLITK), 256>>>(Wo);
    k_reduce<<<3600, 256>>>(query, bo, out);
}

// round 9
// speedup vs baseline: 1.9189x; 1.4515x over previous
#include <cuda_runtime.h>
#include <cuda_fp16.h>
#include <cstdint>

#define DINL __device__ __forceinline__

namespace {
constexpr int NQ   = 3600;    // B*Q
constexpr int KD   = 256;     // query dim
constexpr int NPAR = 32768;   // G * TOTAL
constexpr int TOT  = 8192;
constexpr int SPLITK = 8;
constexpr int WN_ELEMS = 8388608;         // 256*32768 == 32768*256
// K2 smem layout (halfs): per group M[64][72], S[128][40], X/H[32][72]
constexpr int G_M = 64 * 72;              // 4608
constexpr int G_S = 128 * 40;             // 5120
constexpr int G_X = 32 * 72;              // 2304
constexpr int GSTR = G_M + G_S + G_X;     // 12032 halfs
constexpr int K2_SMEM = 2 * GSTR * 2;     // 48128 bytes  (<= 49152 default limit)
}

// scratch (device globals: allocation-free)
__device__ __half g_params[(size_t)NQ * NPAR];              // 236 MB
__device__ __half g_h2[(size_t)NQ * NPAR];                  // 236 MB
__device__ float  g_psum[(size_t)SPLITK * NQ * KD];         // 29.5 MB
__device__ __half g_wp_h[(size_t)WN_ELEMS];                 // 16.7 MB
__device__ __half g_wo_h[(size_t)WN_ELEMS];                 // 16.7 MB

DINL uint32_t smem_u32(const void* p){ return (uint32_t)__cvta_generic_to_shared(p); }

DINL void ldsm_x4(uint32_t r[4], uint32_t a){
    asm volatile("ldmatrix.sync.aligned.m8n8.x4.shared.b16 {%0,%1,%2,%3}, [%4];"
                 : "=r"(r[0]),"=r"(r[1]),"=r"(r[2]),"=r"(r[3]) : "r"(a));
}
DINL void ldsm_x4_t(uint32_t r[4], uint32_t a){
    asm volatile("ldmatrix.sync.aligned.m8n8.x4.trans.shared.b16 {%0,%1,%2,%3}, [%4];"
                 : "=r"(r[0]),"=r"(r[1]),"=r"(r[2]),"=r"(r[3]) : "r"(a));
}
DINL void mma16816(float d[4], const uint32_t a[4], const uint32_t b[2]){
    asm volatile("mma.sync.aligned.m16n8k16.row.col.f32.f16.f16.f32 "
                 "{%0,%1,%2,%3}, {%4,%5,%6,%7}, {%8,%9}, {%0,%1,%2,%3};"
                 : "+f"(d[0]),"+f"(d[1]),"+f"(d[2]),"+f"(d[3])
                 : "r"(a[0]),"r"(a[1]),"r"(a[2]),"r"(a[3]),"r"(b[0]),"r"(b[1]));
}
DINL uint2 cvt4h(float4 v){
    union { __half2 h[2]; uint2 u; } p;
    p.h[0] = __floats2half2_rn(v.x, v.y);
    p.h[1] = __floats2half2_rn(v.z, v.w);
    return p.u;
}

// ---------------------------------------------------------------------------
// K0: fp32 -> fp16 weight conversion. Destination is the device global,
// referenced from DEVICE code (host-side &g_wp_h is the host shadow — bug in
// R6/R8: writes went to host memory via ATS and the device copy stayed 0).
// ---------------------------------------------------------------------------
__global__ __launch_bounds__(256) void k_cvt_wp(const float* __restrict__ src)
{
    size_t i = ((size_t)blockIdx.x * 256 + threadIdx.x) * 4;
    float4 v = *(const float4*)&src[i];
    *(uint2*)&g_wp_h[i] = cvt4h(v);
}
__global__ __launch_bounds__(256) void k_cvt_wo(const float* __restrict__ src)
{
    size_t i = ((size_t)blockIdx.x * 256 + threadIdx.x) * 4;
    float4 v = *(const float4*)&src[i];
    *(uint2*)&g_wo_h[i] = cvt4h(v);
}

// ---------------------------------------------------------------------------
// K1: params = half( query @ Wp + bp )   [3600,256] x [256,32768]
// BM=128, BN=128, BK=32, 8 warps (2m x 4n), fp16 MMA; B read from g_wp_h.
// ---------------------------------------------------------------------------
__global__ __launch_bounds__(256) void k_params(const float* __restrict__ A,
                                                const float* __restrict__ bp)
{
    __shared__ __half As[128][40];    // [m][k], pad 8
    __shared__ __half Bs[32][136];    // [k][n], pad 8

    const int tx = threadIdx.x;
    const int bn = blockIdx.x;        // 256
    const int bm = blockIdx.y;        // 29
    const int lane = tx & 31, wid = tx >> 5;
    const int g8 = lane >> 2, t4 = lane & 3;
    const int wm = (wid >> 2) * 64, wn = (wid & 3) * 32;

    const int arow = tx >> 1, acol = (tx & 1) * 16;
    const int brow = tx >> 3, bcol = (tx & 7) * 16;
    const int gm = bm * 128 + arow;
    const bool av = (gm < NQ);

    const int lr  = (lane & 7) + ((lane >> 3) & 1) * 8;
    const int lc8 = (lane >> 4) * 8;

    float4 apre[4]; uint4 bpre[2];
    #pragma unroll
    for (int i = 0; i < 4; i++)
        apre[i] = av ? *(const float4*)&A[(size_t)gm*KD + acol + 4*i]
                     : make_float4(0.f,0.f,0.f,0.f);
    bpre[0] = *(const uint4*)&g_wp_h[(size_t)brow*NPAR + (size_t)bn*128 + bcol];
    bpre[1] = *(const uint4*)&g_wp_h[(size_t)brow*NPAR + (size_t)bn*128 + bcol + 8];

    float acc[4][4][4];
    #pragma unroll
    for (int i=0;i<4;i++) for (int j=0;j<4;j++) for (int q=0;q<4;q++) acc[i][j][q]=0.f;

    #pragma unroll 1
    for (int ks = 0; ks < 8; ks++){
        #pragma unroll
        for (int i = 0; i < 4; i++)
            *(uint2*)&As[arow][acol + 4*i] = cvt4h(apre[i]);
        *(uint4*)&Bs[brow][bcol]     = bpre[0];
        *(uint4*)&Bs[brow][bcol + 8] = bpre[1];
        __syncthreads();
        if (ks < 7){
            const int k0 = (ks + 1) * 32;
            #pragma unroll
            for (int i = 0; i < 4; i++)
                apre[i] = av ? *(const float4*)&A[(size_t)gm*KD + k0 + acol + 4*i]
                             : make_float4(0.f,0.f,0.f,0.f);
            bpre[0] = *(const uint4*)&g_wp_h[(size_t)(k0+brow)*NPAR + (size_t)bn*128 + bcol];
            bpre[1] = *(const uint4*)&g_wp_h[(size_t)(k0+brow)*NPAR + (size_t)bn*128 + bcol + 8];
        }
        #pragma unroll
        for (int kk = 0; kk < 32; kk += 16){
            uint32_t af[4][4], bf[4][2];
            #pragma unroll
            for (int mi = 0; mi < 4; mi++)
                ldsm_x4(af[mi], smem_u32(&As[wm + mi*16 + lr][kk + lc8]));
            #pragma unroll
            for (int nj = 0; nj < 2; nj++){
                uint32_t r[4];
                ldsm_x4_t(r, smem_u32(&Bs[kk + lr][wn + nj*16 + lc8]));
                bf[nj*2+0][0]=r[0]; bf[nj*2+0][1]=r[1];
                bf[nj*2+1][0]=r[2]; bf[nj*2+1][1]=r[3];
            }
            #pragma unroll
            for (int mi = 0; mi < 4; mi++)
                #pragma unroll
                for (int ni = 0; ni < 4; ni++)
                    mma16816(acc[mi][ni], af[mi], bf[ni]);
        }
        __syncthreads();
    }

    #pragma unroll
    for (int mi = 0; mi < 4; mi++){
        int r0 = bm*128 + wm + mi*16 + g8;
        #pragma unroll
        for (int ni = 0; ni < 4; ni++){
            int c = bn*128 + wn + ni*8 + t4*2;
            float2 bv = *(const float2*)&bp[c];
            if (r0 < NQ)
                *(__half2*)&g_params[(size_t)r0*NPAR + c] =
                    __floats2half2_rn(acc[mi][ni][0]+bv.x, acc[mi][ni][1]+bv.y);
            if (r0 + 8 < NQ)
                *(__half2*)&g_params[(size_t)(r0+8)*NPAR + c] =
                    __floats2half2_rn(acc[mi][ni][2]+bv.x, acc[mi][ni][3]+bv.y);
        }
    }
}

// ---------------------------------------------------------------------------
// K2: per-n mixing with fp16 tensor cores.
// CTA = (gpair, n): 2 groups x 2 warps = 128 threads, 48128B dynamic smem.
// GEMM1: X[32,64]@M[64,64] -> LN -> relu -> H ; GEMM2: S[128,32]@H[32,64]
// -> LN -> relu -> g_h2.  LN stats in fp32.
// ---------------------------------------------------------------------------
__global__ __launch_bounds__(128, 1) void k_mix2(const float* __restrict__ x)
{
    extern __shared__ __half dsm[];
    __shared__ float sR[16];

    const int gpair = blockIdx.x;   // 0,1 -> groups gpair*2 .. gpair*2+1
    const int n = blockIdx.y;
    const int tx = threadIdx.x;
    const int lane = tx & 31, wid = tx >> 5;      // wid 0..3
    const int g = wid >> 1, wg = wid & 1;         // local group, warp-in-group
    const int g8 = lane >> 2, t4 = lane & 3;
    const int lr  = (lane & 7) + ((lane >> 3) & 1) * 8;
    const int lc8 = (lane >> 4) * 8;

    // ---- loads (2 groups) ----
    const __half* pp = g_params + (size_t)n * NPAR + (size_t)gpair * 2 * TOT;
    #pragma unroll
    for (int i = 0; i < 8; i++){                 // M: 2g x 64 rows x 8 uint4
        int idx = i*128 + tx, gg = idx >> 9, rem = idx & 511;
        int row = rem >> 3, col = (rem & 7) * 8;
        *(uint4*)&dsm[gg*GSTR + row*72 + col] =
            *(const uint4*)&pp[(size_t)gg*TOT + row*64 + col];
    }
    #pragma unroll
    for (int i = 0; i < 8; i++){                 // S: 2g x 128 rows x 4 uint4
        int idx = i*128 + tx, gg = idx >> 9, rem = idx & 511;
        int row = rem >> 2, col = (rem & 3) * 8;
        *(uint4*)&dsm[gg*GSTR + G_M + row*40 + col] =
            *(const uint4*)&pp[(size_t)gg*TOT + 4096 + row*32 + col];
    }
    const float* xb = x + (size_t)n * 8192 + (size_t)gpair * 2 * 2048;
    #pragma unroll
    for (int i = 0; i < 8; i++){                 // X: 2g x 32 rows x 16 float4
        int idx = i*128 + tx, gg = idx >> 9, rem = idx & 511;
        int row = rem >> 4, col = (rem & 15) * 4;
        float4 v = *(const float4*)&xb[gg*2048 + row*64 + col];
        *(uint2*)&dsm[gg*GSTR + G_M + G_S + row*72 + col] = cvt4h(v);
    }
    __syncthreads();

    __half* Mg = dsm + g*GSTR;
    __half* Sg = Mg + G_M;
    __half* Xg = Sg + G_S;     // aliased as H after GEMM1

    // ---- GEMM1: C1[32,64] ; warp wg owns rows wg*16..+15 ----
    const int m0 = wg * 16;
    float c1[8][4];
    #pragma unroll
    for (int i=0;i<8;i++) for (int q=0;q<4;q++) c1[i][q]=0.f;
    #pragma unroll
    for (int k = 0; k < 64; k += 16){
        uint32_t a[4], b[8][2];
        ldsm_x4(a, smem_u32(&Xg[(m0 + lr)*72 + k + lc8]));
        #pragma unroll
        for (int nj = 0; nj < 4; nj++){
            uint32_t r[4];
            ldsm_x4_t(r, smem_u32(&Mg[(k + lr)*72 + nj*16 + lc8]));
            b[nj*2+0][0]=r[0]; b[nj*2+0][1]=r[1];
            b[nj*2+1][0]=r[2]; b[nj*2+1][1]=r[3];
        }
        #pragma unroll
        for (int ni = 0; ni < 8; ni++) mma16816(c1[ni], a, b[ni]);
    }
    // ---- LN1 over 2048 ----
    float s = 0.f, s2 = 0.f;
    #pragma unroll
    for (int i=0;i<8;i++) for (int q=0;q<4;q++){ s += c1[i][q]; s2 = fmaf(c1[i][q], c1[i][q], s2); }
    #pragma unroll
    for (int off=16; off>0; off>>=1){
        s  += __shfl_xor_sync(0xffffffffu, s,  off);
        s2 += __shfl_xor_sync(0xffffffffu, s2, off);
    }
    if (lane == 0){ sR[wid*2] = s; sR[wid*2+1] = s2; }
    __syncthreads();
    {
        float S1 = sR[g*4+0] + sR[g*4+2];
        float S2 = sR[g*4+1] + sR[g*4+3];
        float mu = S1 * (1.f/2048.f);
        float rstd = rsqrtf(S2 * (1.f/2048.f) - mu*mu + 1e-5f);
        #pragma unroll
        for (int ni = 0; ni < 8; ni++){
            int col = ni*8 + t4*2;
            *(__half2*)&Xg[(m0 + g8)*72 + col] =
                __floats2half2_rn(fmaxf(0.f,(c1[ni][0]-mu)*rstd), fmaxf(0.f,(c1[ni][1]-mu)*rstd));
            *(__half2*)&Xg[(m0 + g8 + 8)*72 + col] =
                __floats2half2_rn(fmaxf(0.f,(c1[ni][2]-mu)*rstd), fmaxf(0.f,(c1[ni][3]-mu)*rstd));
        }
    }
    __syncthreads();

    // ---- GEMM2: C2[128,64] ; warp wg owns rows wg*64..+63 ----
    const int q0 = wg * 64;
    float c2[4][8][4];
    #pragma unroll
    for (int mi=0;mi<4;mi++) for (int ni=0;ni<8;ni++) for (int q=0;q<4;q++) c2[mi][ni][q]=0.f;
    #pragma unroll
    for (int k = 0; k < 32; k += 16){
        uint32_t a2[4][4], b2[8][2];
        #pragma unroll
        for (int mi = 0; mi < 4; mi++)
            ldsm_x4(a2[mi], smem_u32(&Sg[(q0 + mi*16 + lr)*40 + k + lc8]));
        #pragma unroll
        for (int nj = 0; nj < 4; nj++){
            uint32_t r[4];
            ldsm_x4_t(r, smem_u32(&Xg[(k + lr)*72 + nj*16 + lc8]));
            b2[nj*2+0][0]=r[0]; b2[nj*2+0][1]=r[1];
            b2[nj*2+1][0]=r[2]; b2[nj*2+1][1]=r[3];
        }
        #pragma unroll
        for (int mi = 0; mi < 4; mi++)
            #pragma unroll
            for (int ni = 0; ni < 8; ni++)
                mma16816(c2[mi][ni], a2[mi], b2[ni]);
    }
    // ---- LN2 over 8192 ----
    s = 0.f; s2 = 0.f;
    #pragma unroll
    for (int mi=0;mi<4;mi++) for (int ni=0;ni<8;ni++) for (int q=0;q<4;q++){
        s += c2[mi][ni][q]; s2 = fmaf(c2[mi][ni][q], c2[mi][ni][q], s2);
    }
    #pragma unroll
    for (int off=16; off>0; off>>=1){
        s  += __shfl_xor_sync(0xffffffffu, s,  off);
        s2 += __shfl_xor_sync(0xffffffffu, s2, off);
    }
    if (lane == 0){ sR[wid*2] = s; sR[wid*2+1] = s2; }
    __syncthreads();
    float S1 = sR[g*4+0] + sR[g*4+2];
    float S2 = sR[g*4+1] + sR[g*4+3];
    float mu = S1 * (1.f/8192.f);
    float rstd = rsqrtf(S2 * (1.f/8192.f) - mu*mu + 1e-5f);

    __half* outp = g_h2 + (size_t)n*NPAR + (size_t)(gpair*2 + g)*TOT;
    #pragma unroll
    for (int mi = 0; mi < 4; mi++){
        int r0 = q0 + mi*16 + g8;
        #pragma unroll
        for (int ni = 0; ni < 8; ni++){
            int col = ni*8 + t4*2;
            *(__half2*)&outp[r0*64 + col] =
                __floats2half2_rn(fmaxf(0.f,(c2[mi][ni][0]-mu)*rstd), fmaxf(0.f,(c2[mi][ni][1]-mu)*rstd));
            *(__half2*)&outp[(r0+8)*64 + col] =
                __floats2half2_rn(fmaxf(0.f,(c2[mi][ni][2]-mu)*rstd), fmaxf(0.f,(c2[mi][ni][3]-mu)*rstd));
        }
    }
}

// ---------------------------------------------------------------------------
// K3: psum[sk] = h2[:, sk-slice] @ Wo[sk-slice, :]
// BM=128, BN=128, BK=32, fp16 MMA, split-K=8; B read from g_wo_h.
// ---------------------------------------------------------------------------
__global__ __launch_bounds__(256) void k_proj()
{
    __shared__ __half As[128][40];
    __shared__ __half Bs[32][136];

    const int tx = threadIdx.x;
    const int bm = blockIdx.x;      // 29
    const int bn = blockIdx.y;      // 2
    const int sk = blockIdx.z;      // 8
    const int lane = tx & 31, wid = tx >> 5;
    const int g8 = lane >> 2, t4 = lane & 3;
    const int wm = (wid >> 2) * 64, wn = (wid & 3) * 32;

    const int arow = tx >> 1, acol = (tx & 1) * 16;
    const int brow = tx >> 3, bcol = (tx & 7) * 16;
    const int gm = bm * 128 + arow;
    const bool av = (gm < NQ);
    const int kbase = sk * 4096;

    const int lr  = (lane & 7) + ((lane >> 3) & 1) * 8;
    const int lc8 = (lane >> 4) * 8;

    uint4 apre[2], bpre[2];
    #pragma unroll
    for (int i = 0; i < 2; i++)
        apre[i] = av ? *(const uint4*)&g_h2[(size_t)gm*NPAR + kbase + acol + 8*i]
                     : make_uint4(0u,0u,0u,0u);
    bpre[0] = *(const uint4*)&g_wo_h[(size_t)(kbase+brow)*KD + bn*128 + bcol];
    bpre[1] = *(const uint4*)&g_wo_h[(size_t)(kbase+brow)*KD + bn*128 + bcol + 8];

    float acc[4][4][4];
    #pragma unroll
    for (int i=0;i<4;i++) for (int j=0;j<4;j++) for (int q=0;q<4;q++) acc[i][j][q]=0.f;

    #pragma unroll 1
    for (int ks = 0; ks < 128; ks++){
        #pragma unroll
        for (int i = 0; i < 2; i++)
            *(uint4*)&As[arow][acol + 8*i] = apre[i];
        *(uint4*)&Bs[brow][bcol]     = bpre[0];
        *(uint4*)&Bs[brow][bcol + 8] = bpre[1];
        __syncthreads();
        if (ks < 127){
            const int k0 = kbase + (ks + 1) * 32;
            #pragma unroll
            for (int i = 0; i < 2; i++)
                apre[i] = av ? *(const uint4*)&g_h2[(size_t)gm*NPAR + k0 + acol + 8*i]
                             : make_uint4(0u,0u,0u,0u);
            bpre[0] = *(const uint4*)&g_wo_h[(size_t)(k0+brow)*KD + bn*128 + bcol];
            bpre[1] = *(const uint4*)&g_wo_h[(size_t)(k0+brow)*KD + bn*128 + bcol + 8];
        }
        #pragma unroll
        for (int kk = 0; kk < 32; kk += 16){
            uint32_t af[4][4], bf[4][2];
            #pragma unroll
            for (int mi = 0; mi < 4; mi++)
                ldsm_x4(af[mi], smem_u32(&As[wm + mi*16 + lr][kk + lc8]));
            #pragma unroll
            for (int nj = 0; nj < 2; nj++){
                uint32_t r[4];
                ldsm_x4_t(r, smem_u32(&Bs[kk + lr][wn + nj*16 + lc8]));
                bf[nj*2+0][0]=r[0]; bf[nj*2+0][1]=r[1];
                bf[nj*2+1][0]=r[2]; bf[nj*2+1][1]=r[3];
            }
            #pragma unroll
            for (int mi = 0; mi < 4; mi++)
                #pragma unroll
                for (int ni = 0; ni < 4; ni++)
                    mma16816(acc[mi][ni], af[mi], bf[ni]);
        }
        __syncthreads();
    }

    #pragma unroll
    for (int mi = 0; mi < 4; mi++){
        int r0 = bm*128 + wm + mi*16 + g8;
        #pragma unroll
        for (int ni = 0; ni < 4; ni++){
            int c = bn*128 + wn + ni*8 + t4*2;
            if (r0 < NQ)
                *(float2*)&g_psum[((size_t)sk*NQ + r0)*KD + c] =
                    make_float2(acc[mi][ni][0], acc[mi][ni][1]);
            if (r0 + 8 < NQ)
                *(float2*)&g_psum[((size_t)sk*NQ + (r0+8))*KD + c] =
                    make_float2(acc[mi][ni][2], acc[mi][ni][3]);
        }
    }
}

// ---------------------------------------------------------------------------
// K4: out = query + bo + sum_sk psum[sk]
// ---------------------------------------------------------------------------
__global__ __launch_bounds__(256) void k_reduce(const float* __restrict__ query,
                                                const float* __restrict__ bo,
                                                float* __restrict__ out)
{
    int idx = blockIdx.x * 256 + threadIdx.x;
    float v = query[idx] + bo[idx & 255];
    #pragma unroll
    for (int s = 0; s < SPLITK; s++)
        v += g_psum[(size_t)s * NQ * KD + idx];
    out[idx] = v;
}

// ---------------------------------------------------------------------------
extern "C" void kernel_launch(void* const* d_in, const int* in_sizes, int n_in,
                              void* d_out, int out_size)
{
    const float* x     = (const float*)d_in[0];
    const float* query = (const float*)d_in[1];
    const float* Wp    = (const float*)d_in[2];
    const float* bp    = (const float*)d_in[3];
    const float* Wo    = (const float*)d_in[4];
    const float* bo    = (const float*)d_in[5];
    float* out = (float*)d_out;

    k_cvt_wp<<<WN_ELEMS/1024, 256>>>(Wp);
    k_cvt_wo<<<WN_ELEMS/1024, 256>>>(Wo);
    k_params<<<dim3(256, 29), 256>>>(query, bp);
    k_mix2<<<dim3(2, 3600), 128, K2_SMEM>>>(x);
    k_proj<<<dim3(29, 2, SPLITK), 256>>>();
    k_reduce<<<3600, 256>>>(query, bo, out);
}